// round 17
// baseline (speedup 1.0000x reference)
#include <cuda_runtime.h>
#include <math.h>
#include <stdint.h>

#define HD 128
#define NN 256
#define NB 16

// Scratch (allocation-free rule: __device__ globals)
__device__ float g_h[NN][HD];    // layer-2 output (relu), batch 0
__device__ float g_P[32][HD];    // per-block partial sums of dinv*h (scan)
__device__ float g_A0[NN][HD];   // h3 @ W1a + b1   (batch 0)
__device__ float g_B0[NN][HD];   // h3 @ W1b        (batch 0)
__device__ float g_pb[NB];       // constant edge prob per batch (b>=1)

// 32KB stage load via cp.async (8 x 16B per thread, 256 threads)
__device__ __forceinline__ void cp_stage(uint32_t dst, const float* src, int tid) {
    const char* s = (const char*)src + tid * 16;
    uint32_t d = dst + tid * 16;
#pragma unroll
    for (int i = 0; i < 8; i++)
        asm volatile("cp.async.cg.shared.global [%0], [%1], 16;"
                     :: "r"(d + i * 4096), "l"(s + i * 4096));
    asm volatile("cp.async.commit_group;" ::: "memory");
}
#define CPWG3() asm volatile("cp.async.wait_group 3;" ::: "memory")
#define CPWG2() asm volatile("cp.async.wait_group 2;" ::: "memory")
#define CPWG1() asm volatile("cp.async.wait_group 1;" ::: "memory")
#define CPWG0() asm volatile("cp.async.wait_group 0;" ::: "memory")

// block-wide exclusive prefix scan over 256 values (one per thread)
__device__ __forceinline__ float blk_exscan256(float v, int tid, float* ws) {
    float x = v;
#pragma unroll
    for (int o = 1; o < 32; o <<= 1) {
        float y = __shfl_up_sync(0xffffffffu, x, o);
        if ((tid & 31) >= o) x += y;
    }
    if ((tid & 31) == 31) ws[tid >> 5] = x;
    __syncthreads();
    float add = 0.f;
#pragma unroll
    for (int w = 0; w < 8; w++) add += (w < (tid >> 5)) ? ws[w] : 0.f;
    __syncthreads();
    return (x - v) + add;
}

// ---------------------------------------------------------------------------
// K1: batch-0 ONLY. 32 blocks. ALL weight loads (Wg0 both halves + layer-2
// both halves = 128KB) issued via cp.async at t=0; emb weights front-loaded
// into registers. Table build + emb overlap the loads; u computes from smem
// (no exposed mid-kernel latency). Closed-form layer-1 prefix (O(log)).
// grid 32 x 256, dynamic smem 128KB
// ---------------------------------------------------------------------------
__global__ void __launch_bounds__(256, 1)
k1(const float* __restrict__ z, const float* __restrict__ We,
   const float* __restrict__ be, const float* __restrict__ Wg,
   const float* __restrict__ bg) {
    extern __shared__ __align__(16) float buf[];   // 4 x 8192 floats
    __shared__ __align__(16) float gs[8][HD];
    __shared__ __align__(16) float hs[8][HD];
    __shared__ __align__(16) float4 pred[8][32];
    __shared__ float zs[64];
    __shared__ float vv[HD];
    __shared__ float uu[HD];
    __shared__ float ds[NN];     // dinv[j]
    __shared__ float scT[NN];    // sc[j] (monotone increasing)
    __shared__ float P1[NN];     // exclusive prefix of dinv[j]*sc[j]
    __shared__ float P2[NN];     // exclusive prefix of dinv[j]  (= Dex)
    __shared__ float ws[8];
    int tid = threadIdx.x, bk = blockIdx.x;
    int warp = tid >> 5, lane = tid & 31;
    uint32_t sb = (uint32_t)__cvta_generic_to_shared(buf);

    // let k2 launch + run its independent work while we execute (PDL)
    cudaTriggerProgrammaticLaunchCompletion();

    // stage Wg0 halves + layer-2 weight halves (all async, t=0)
    cp_stage(sb,           Wg,                      tid);   // g0: Wg0 h0
    cp_stage(sb + 32768u,  Wg + 64 * HD,            tid);   // g1: Wg0 h1
    cp_stage(sb + 65536u,  Wg + HD * HD,            tid);   // g2: L2W h0
    cp_stage(sb + 98304u,  Wg + HD * HD + 64 * HD,  tid);   // g3: L2W h1

    // front-load emb weight LDGs (latency hidden by table build below)
    const float4* We4 = (const float4*)We;
    float4 wreg[8];
#pragma unroll
    for (int i = 0; i < 8; i++) wreg[i] = We4[(warp * 8 + i) * 32 + lane];
    if (tid < 64) zs[tid] = z[tid];

    // ---- build d-independent tables: ds, Dex->P2, sc, P1 (O(log) scans) ----
    float dv = rsqrtf((float)(tid + 1));
    ds[tid] = dv;
    float dex = blk_exscan256(dv, tid, ws);
    P2[tid] = dex;
    float sc = fmaf(dv, dex, dv * dv);
    scT[tid] = sc;
    float p1 = blk_exscan256(dv * sc, tid, ws);
    P1[tid] = p1;
    __syncthreads();                                  // tables + zs visible

    // emb FMAs (weights already in regs)
    {
        float4 pe = make_float4(0.f, 0.f, 0.f, 0.f);
#pragma unroll
        for (int i = 0; i < 8; i++) {
            float zk = zs[warp * 8 + i];
            pe.x = fmaf(zk, wreg[i].x, pe.x); pe.y = fmaf(zk, wreg[i].y, pe.y);
            pe.z = fmaf(zk, wreg[i].z, pe.z); pe.w = fmaf(zk, wreg[i].w, pe.w);
        }
        pred[warp][lane] = pe;
    }
    __syncthreads();
    if (tid < 32) {
        float4 s = pred[0][tid];
#pragma unroll
        for (int w = 1; w < 8; w++) {
            float4 p = pred[w][tid];
            s.x += p.x; s.y += p.y; s.z += p.z; s.w += p.w;
        }
        float4 b4 = ((const float4*)be)[tid];
        s.x += b4.x; s.y += b4.y; s.z += b4.z; s.w += b4.w;
        ((float4*)vv)[tid] = s;
    }
    // wait for Wg0 halves (g0,g1) while emb reduce finishes
    CPWG2();
    __syncthreads();

    // u = vv @ Wg0 from smem: warp k-split (16 k per warp), zero exposed latency
    {
        float4 pu = make_float4(0.f, 0.f, 0.f, 0.f);
#pragma unroll
        for (int i = 0; i < 16; i++) {
            int k = warp * 16 + i;                          // 0..127
            const float4* Ws4 = (const float4*)(buf + (k >> 6) * 8192);
            float vk = vv[k];
            float4 w4 = Ws4[(k & 63) * 32 + lane];
            pu.x = fmaf(vk, w4.x, pu.x); pu.y = fmaf(vk, w4.y, pu.y);
            pu.z = fmaf(vk, w4.z, pu.z); pu.w = fmaf(vk, w4.w, pu.w);
        }
        pred[warp][lane] = pu;
    }
    __syncthreads();
    if (tid < 32) {
        float4 s = pred[0][tid];
#pragma unroll
        for (int w = 1; w < 8; w++) {
            float4 p = pred[w][tid];
            s.x += p.x; s.y += p.y; s.z += p.z; s.w += p.w;
        }
        ((float4*)uu)[tid] = s;
    }
    __syncthreads();

    // ---- closed-form prefix + 8 local rows ----
    if (tid < 128) {
        int d = tid;
        float uf = uu[d];
        float bg0 = bg[d];
        int base = bk * 8;
        float c;
        if (base == 0) {
            c = 0.f;
        } else if (uf > 0.f) {
            // active j: sc[j]*uf + bg0 > 0, increasing -> suffix [lo, base)
            int lo = 0, hi = base;
            while (lo < hi) {
                int mid = (lo + hi) >> 1;
                if (fmaf(scT[mid], uf, bg0) > 0.f) hi = mid; else lo = mid + 1;
            }
            c = uf * (P1[base] - P1[lo]) + bg0 * (P2[base] - P2[lo]);
        } else if (uf < 0.f) {
            // expression decreasing -> active prefix [0, lo)
            int lo = 0, hi = base;
            while (lo < hi) {
                int mid = (lo + hi) >> 1;
                if (fmaf(scT[mid], uf, bg0) > 0.f) lo = mid + 1; else hi = mid;
            }
            c = uf * P1[lo] + bg0 * P2[lo];
        } else {
            c = (bg0 > 0.f) ? bg0 * P2[base] : 0.f;
        }
        // local 8 rows (same recurrence as reference)
#pragma unroll
        for (int j = 0; j < 8; j++) {
            int n = base + j;
            float dvj = ds[n];
            float h1 = fmaxf(fmaf(scT[n], uf, bg0), 0.f);
            gs[j][d] = fmaf(dvj, c, dvj * dvj * h1);
            c = fmaf(dvj, h1, c);
        }
    }
    __syncthreads();

    // layer-2 GEMM: warp-per-row, 2 staged halves (g2, g3)
    float4 acc = ((const float4*)(bg + HD))[lane];
    CPWG1();   // g2 done (g3 may still be in flight)
    {
        const float4* Ws4 = (const float4*)(buf + 2 * 8192);
#pragma unroll 8
        for (int k = 0; k < 64; k++) {
            float g = gs[warp][k];
            float4 w = Ws4[k * 32 + lane];
            acc.x = fmaf(g, w.x, acc.x); acc.y = fmaf(g, w.y, acc.y);
            acc.z = fmaf(g, w.z, acc.z); acc.w = fmaf(g, w.w, acc.w);
        }
    }
    CPWG0();
    {
        const float4* Ws4 = (const float4*)(buf + 3 * 8192);
#pragma unroll 8
        for (int k = 0; k < 64; k++) {
            float g = gs[warp][64 + k];
            float4 w = Ws4[k * 32 + lane];
            acc.x = fmaf(g, w.x, acc.x); acc.y = fmaf(g, w.y, acc.y);
            acc.z = fmaf(g, w.z, acc.z); acc.w = fmaf(g, w.w, acc.w);
        }
    }
    acc.x = fmaxf(acc.x, 0.f); acc.y = fmaxf(acc.y, 0.f);
    acc.z = fmaxf(acc.z, 0.f); acc.w = fmaxf(acc.w, 0.f);
    int base = bk * 8;
    ((float4*)&g_h[base + warp][0])[lane] = acc;
    float dj = ds[base + warp];
    ((float4*)&hs[warp][0])[lane] = make_float4(acc.x * dj, acc.y * dj, acc.z * dj, acc.w * dj);
    __syncthreads();
    if (tid < HD) {
        float sum = 0.f;
#pragma unroll
        for (int w = 0; w < 8; w++) sum += hs[w][tid];
        g_P[bk][tid] = sum;
    }
}

// ---------------------------------------------------------------------------
// K2: blocks 0..63 : scan -> layer-3 GEMM+relu -> W1a|W1b GEMM (4 stages);
//                    waits on k1 only AFTER issuing its weight prefetch.
//     blocks 64..78: FULL chain for b = blk-63 (independent of k1, no
//                    gridDependencySynchronize). grid 79 x 256, smem 128KB
// ---------------------------------------------------------------------------
__global__ void __launch_bounds__(256, 1)
k2(const float* __restrict__ z, const float* __restrict__ We,
   const float* __restrict__ be, const float* __restrict__ Wg,
   const float* __restrict__ bg, const float* __restrict__ W1a,
   const float* __restrict__ W1b, const float* __restrict__ b1,
   const float* __restrict__ W2, const float* __restrict__ b2) {
    extern __shared__ __align__(16) float buf[];   // 4 x 8192 floats
    __shared__ __align__(16) float gs[8][HD];
    __shared__ __align__(16) float hs[8][HD];
    __shared__ float zs[64];
    __shared__ float vv[HD];
    __shared__ float red[2][HD];
    __shared__ float wsum[8];
    int tid = threadIdx.x, blk = blockIdx.x;
    int d = tid & 127, hf = tid >> 7;
    int warp = tid >> 5, lane = tid & 31;
    uint32_t sb = (uint32_t)__cvta_generic_to_shared(buf);
    const float* Wg2 = Wg + 2 * HD * HD;

    cudaTriggerProgrammaticLaunchCompletion();

    if (blk < 64) {
        int bk2 = blk >> 1, sel = blk & 1;
        int base = bk2 * 8;
        const float* WX = sel ? W1b : W1a;
        const float* srcs[4] = { Wg2, Wg2 + 64 * HD, WX, WX + 64 * HD };
#pragma unroll
        for (int i = 0; i < 4; i++) cp_stage(sb + i * 32768u, srcs[i], tid);

        cudaGridDependencySynchronize();

        if (tid < 128) {
            float hr[8];
#pragma unroll
            for (int j = 0; j < 8; j++) hr[j] = g_h[base + j][tid];
            float ca[4] = {0.f, 0.f, 0.f, 0.f};
#pragma unroll
            for (int p = 0; p < 32; p++) {
                float v = g_P[p][tid];
                ca[p & 3] += (p < bk2) ? v : 0.f;
            }
            float c = (ca[0] + ca[1]) + (ca[2] + ca[3]);
#pragma unroll
            for (int j = 0; j < 8; j++) {
                float dv = rsqrtf((float)(base + j + 1));
                gs[j][tid] = fmaf(dv, c, dv * dv * hr[j]);
                c = fmaf(dv, hr[j], c);
            }
        }
        float4 acc = ((const float4*)(bg + 2 * HD))[lane];
        float4 aX = sel ? make_float4(0.f, 0.f, 0.f, 0.f)
                        : ((const float4*)b1)[lane];
#pragma unroll
        for (int s = 0; s < 4; s++) {
            if (s == 0) { CPWG3(); } else if (s == 1) { CPWG2(); }
            else if (s == 2) { CPWG1(); } else { CPWG0(); }
            __syncthreads();
            const float4* Ws4 = (const float4*)(buf + s * 8192);
            const float* in = (s < 2) ? &gs[warp][0] : &hs[warp][0];
            int ko = (s & 1) * 64;
            float4 a = (s < 2) ? acc : aX;
#pragma unroll 8
            for (int k = 0; k < 64; k++) {
                float g = in[ko + k];
                float4 w = Ws4[k * 32 + lane];
                a.x = fmaf(g, w.x, a.x); a.y = fmaf(g, w.y, a.y);
                a.z = fmaf(g, w.z, a.z); a.w = fmaf(g, w.w, a.w);
            }
            if (s < 2) acc = a; else aX = a;
            if (s == 1) {
                acc.x = fmaxf(acc.x, 0.f); acc.y = fmaxf(acc.y, 0.f);
                acc.z = fmaxf(acc.z, 0.f); acc.w = fmaxf(acc.w, 0.f);
                ((float4*)&hs[warp][0])[lane] = acc;
            }
            __syncthreads();
        }
        if (sel) ((float4*)&g_B0[base + warp][0])[lane] = aX;
        else     ((float4*)&g_A0[base + warp][0])[lane] = aX;
    } else {
        int b = blk - 63;
        const float* srcs[11] = { We,
            Wg,               Wg + 64 * HD,
            Wg + HD * HD,     Wg + HD * HD + 64 * HD,
            Wg2,              Wg2 + 64 * HD,
            W1a,              W1a + 64 * HD,
            W1b,              W1b + 64 * HD };
#pragma unroll
        for (int i = 0; i < 4; i++) cp_stage(sb + i * 32768u, srcs[i], tid);
        if (tid < 64) zs[tid] = z[b * 64 + tid];
        float accL = 0.f, aA = 0.f, aB = 0.f, aAf = 0.f;
#pragma unroll
        for (int s = 0; s < 11; s++) {
            if (s <= 7) { CPWG3(); } else if (s == 8) { CPWG2(); }
            else if (s == 9) { CPWG1(); } else { CPWG0(); }
            __syncthreads();
            const float* B = buf + (s & 3) * 8192;
            if (s == 0) {
                float p0 = 0.f, p1 = 0.f; int kb = hf * 32;
#pragma unroll 8
                for (int kk = 0; kk < 32; kk += 2) {
                    p0 = fmaf(zs[kb + kk],     B[(kb + kk) * HD + d],     p0);
                    p1 = fmaf(zs[kb + kk + 1], B[(kb + kk + 1) * HD + d], p1);
                }
                red[hf][d] = p0 + p1;
                __syncthreads();
                if (tid < 128) vv[d] = red[0][d] + red[1][d] + be[d];
            } else {
                int g = (s - 1) >> 1, hh = (s - 1) & 1;
                float p0 = 0.f, p1 = 0.f; int kb = hf * 32;
#pragma unroll 8
                for (int kk = 0; kk < 32; kk += 2) {
                    p0 = fmaf(vv[hh * 64 + kb + kk],     B[(kb + kk) * HD + d],     p0);
                    p1 = fmaf(vv[hh * 64 + kb + kk + 1], B[(kb + kk + 1) * HD + d], p1);
                }
                float pt = p0 + p1;
                if (s <= 6) accL += pt;
                else if (s <= 8) aA += pt;
                else aB += pt;
                if (hh == 1 && g < 3) {
                    red[hf][d] = accL;
                    __syncthreads();
                    if (tid < 128) vv[d] = fmaxf(red[0][d] + red[1][d] + bg[g * HD + d], 0.f);
                    accL = 0.f;
                }
                if (s == 8) {
                    red[hf][d] = aA;
                    __syncthreads();
                    if (tid < 128) aAf = red[0][d] + red[1][d] + b1[d];
                }
            }
            __syncthreads();
            if (s + 4 < 11) cp_stage(sb + ((s + 4) & 3) * 32768u, srcs[s + 4], tid);
        }
        red[hf][d] = aB;
        __syncthreads();
        float t = 0.f;
        if (tid < 128) t = fmaxf(aAf + red[0][d] + red[1][d], 0.f) * W2[d];
        for (int off = 16; off > 0; off >>= 1)
            t += __shfl_down_sync(0xffffffffu, t, off);
        if ((tid & 31) == 0) wsum[tid >> 5] = t;
        __syncthreads();
        if (tid == 0) {
            float ssum = wsum[0] + wsum[1] + wsum[2] + wsum[3]
                       + wsum[4] + wsum[5] + wsum[6] + wsum[7] + b2[0];
            g_pb[b] = 1.f / (1.f + __expf(-ssum));
        }
    }
}

// ---------------------------------------------------------------------------
// K3: blocks 0..135 : batch-0 pairwise tiles (16x16, upper triangle, mirrored)
//     blocks 136..147: constant fill for b>=1 (320 rows each, diag 0)
// PDL: W2/b2 staged before the grid-dependency sync. grid 148 x 256
// ---------------------------------------------------------------------------
__global__ void k3(const float* __restrict__ W2, const float* __restrict__ b2,
                   float* __restrict__ out) {
    int tid = threadIdx.x;
    int blk = blockIdx.x;
    if (blk < 136) {
        int ti = 0, rem = blk;
        while (rem >= 16 - ti) { rem -= 16 - ti; ti++; }
        int tj = ti + rem;

        __shared__ __align__(16) float a_sh[16][132];
        __shared__ __align__(16) float b_sh[16][132];
        __shared__ __align__(16) float w2s[HD];
        __shared__ float b2s;
        __shared__ float tile[16][17];
        if (tid < HD) w2s[tid] = W2[tid];
        if (tid == 0) b2s = b2[0];

        cudaGridDependencySynchronize();

        for (int i = tid; i < 512; i += 256) {
            int r = i >> 5, d4 = i & 31;
            ((float4*)&a_sh[r][0])[d4] = ((const float4*)&g_A0[ti * 16 + r][0])[d4];
            ((float4*)&b_sh[r][0])[d4] = ((const float4*)&g_B0[tj * 16 + r][0])[d4];
        }
        __syncthreads();

        int il = tid >> 4, jl = tid & 15;
        const float4* a4 = (const float4*)&a_sh[il][0];
        const float4* b4 = (const float4*)&b_sh[jl][0];
        const float4* w4 = (const float4*)w2s;
        float ac0 = 0.f, ac1 = 0.f, ac2 = 0.f, ac3 = 0.f;
#pragma unroll
        for (int qd = 0; qd < 8; qd++) {
            { float4 a=a4[qd],    b=b4[qd],    w=w4[qd];
              ac0 = fmaf(fmaxf(a.x+b.x,0.f),w.x,ac0); ac0 = fmaf(fmaxf(a.y+b.y,0.f),w.y,ac0);
              ac0 = fmaf(fmaxf(a.z+b.z,0.f),w.z,ac0); ac0 = fmaf(fmaxf(a.w+b.w,0.f),w.w,ac0); }
            { float4 a=a4[qd+8],  b=b4[qd+8],  w=w4[qd+8];
              ac1 = fmaf(fmaxf(a.x+b.x,0.f),w.x,ac1); ac1 = fmaf(fmaxf(a.y+b.y,0.f),w.y,ac1);
              ac1 = fmaf(fmaxf(a.z+b.z,0.f),w.z,ac1); ac1 = fmaf(fmaxf(a.w+b.w,0.f),w.w,ac1); }
            { float4 a=a4[qd+16], b=b4[qd+16], w=w4[qd+16];
              ac2 = fmaf(fmaxf(a.x+b.x,0.f),w.x,ac2); ac2 = fmaf(fmaxf(a.y+b.y,0.f),w.y,ac2);
              ac2 = fmaf(fmaxf(a.z+b.z,0.f),w.z,ac2); ac2 = fmaf(fmaxf(a.w+b.w,0.f),w.w,ac2); }
            { float4 a=a4[qd+24], b=b4[qd+24], w=w4[qd+24];
              ac3 = fmaf(fmaxf(a.x+b.x,0.f),w.x,ac3); ac3 = fmaf(fmaxf(a.y+b.y,0.f),w.y,ac3);
              ac3 = fmaf(fmaxf(a.z+b.z,0.f),w.z,ac3); ac3 = fmaf(fmaxf(a.w+b.w,0.f),w.w,ac3); }
        }
        float accv = (ac0 + ac1) + (ac2 + ac3);
        tile[il][jl] = 1.f / (1.f + __expf(-(accv + b2s)));
        __syncthreads();

        int r = tid >> 4, c = tid & 15;
        if (ti == tj) {
            float vo = (r < c) ? tile[r][c] : ((r > c) ? tile[c][r] : 0.f);
            out[((size_t)(ti * 16 + r)) * NN + ti * 16 + c] = vo;
        } else {
            out[((size_t)(ti * 16 + r)) * NN + tj * 16 + c] = tile[r][c];
            out[((size_t)(tj * 16 + r)) * NN + ti * 16 + c] = tile[c][r];
        }
    } else {
        __shared__ float pbs[NB];
        cudaGridDependencySynchronize();
        if (tid < NB) pbs[tid] = g_pb[tid];
        __syncthreads();
        int fid = blk - 136;
        int f4base = fid * 20480;
#pragma unroll 4
        for (int t = 0; t < 80; t++) {
            int idx = f4base + t * 256 + tid;
            int gr = idx >> 6;
            int c4 = idx & 63;
            int b = (gr >> 8) + 1;
            int i = gr & 255;
            float p = pbs[b];
            int j0 = c4 * 4;
            float4 vo;
            vo.x = (i == j0 + 0) ? 0.f : p;
            vo.y = (i == j0 + 1) ? 0.f : p;
            vo.z = (i == j0 + 2) ? 0.f : p;
            vo.w = (i == j0 + 3) ? 0.f : p;
            ((float4*)out)[((size_t)b * NN * NN + (size_t)i * NN) / 4 + c4] = vo;
        }
    }
}

// ---------------------------------------------------------------------------
extern "C" void kernel_launch(void* const* d_in, const int* in_sizes, int n_in,
                              void* d_out, int out_size) {
    const float* z   = (const float*)d_in[0];
    const float* We  = (const float*)d_in[1];
    const float* be  = (const float*)d_in[2];
    const float* Wg  = (const float*)d_in[3];
    const float* bg  = (const float*)d_in[4];
    const float* W1a = (const float*)d_in[5];
    const float* W1b = (const float*)d_in[6];
    const float* b1  = (const float*)d_in[7];
    const float* W2  = (const float*)d_in[8];
    const float* b2  = (const float*)d_in[9];
    float* out = (float*)d_out;

    cudaFuncSetAttribute(k1, cudaFuncAttributeMaxDynamicSharedMemorySize, 131072);
    cudaFuncSetAttribute(k2, cudaFuncAttributeMaxDynamicSharedMemorySize, 131072);

    k1<<<32, 256, 131072>>>(z, We, be, Wg, bg);

    cudaLaunchAttribute attrs[1];
    attrs[0].id = cudaLaunchAttributeProgrammaticStreamSerialization;
    attrs[0].val.programmaticStreamSerializationAllowed = 1;

    {
        cudaLaunchConfig_t cfg = {};
        cfg.gridDim = dim3(79);
        cfg.blockDim = dim3(256);
        cfg.dynamicSmemBytes = 131072;
        cfg.stream = 0;
        cfg.attrs = attrs;
        cfg.numAttrs = 1;
        cudaLaunchKernelEx(&cfg, k2, z, We, be, Wg, bg, W1a, W1b, b1, W2, b2);
    }
    {
        cudaLaunchConfig_t cfg = {};
        cfg.gridDim = dim3(148);
        cfg.blockDim = dim3(256);
        cfg.dynamicSmemBytes = 0;
        cfg.stream = 0;
        cfg.attrs = attrs;
        cfg.numAttrs = 1;
        cudaLaunchKernelEx(&cfg, k3, W2, b2, out);
    }
}